// round 16
// baseline (speedup 1.0000x reference)
#include <cuda_runtime.h>
#include <math.h>

#define KD 64
#define MDIM 256
#define VDIM 5000
#define LMBDA 0.001f
#define NITER 3
#define SH2 68     // staging stride (floats)

// ---------------- device scratch ----------------
__device__ float g_AP[2][KD * MDIM];     // [0]=A=tx@fx, [1]=Py=ty@fy (zeroed by prev solve)
__device__ float g_S[KD * KD];           // inv(sx)
__device__ float g_Sy[KD * KD];          // inv(sy)
__device__ float g_H[KD * KD];           // sy^T sy
__device__ float g_G[KD * KD];           // A A^T
__device__ float g_T1[KD * KD];          // Py A^T
__device__ float g_Mcat[KD * 192];       // [M2 | M1 | M0] (each symmetric)
__device__ float g_NT[192 * KD];         // NT[c][k] = Ncat[k][c], Ncat=[N2|N1|N0]
__device__ float g_Hinv[KD * KD];
__device__ float g_Ginv[KD * KD];
__device__ float g_HL[KD * KD];          // H ly + ly H   (symmetric)
__device__ float g_LHL[KD * KD];         // ly H ly       (symmetric)
__device__ float g_LP[KD * 128];         // [-Hinv HL | Hinv LHL]
__device__ float g_X0[KD * KD];
__device__ float g_Vd[2][KD * 128];      // double-buffered V cols 64..191

// ---------------- sync ----------------
__device__ __forceinline__ void cluster_sync_fence() {
  __threadfence();
  asm volatile("barrier.cluster.arrive.aligned;" ::: "memory");
  asm volatile("barrier.cluster.wait.aligned;" ::: "memory");
}

// ---------------- helpers ----------------

// C[a0..a0+15][0..63] = scale * sum_k P[a][k]*Q[b][k]; strides multiples of 4.
// Requires blockDim.x == 256.
__device__ __forceinline__ void mm_nt_16(
    const float* __restrict__ P, int ldp,
    const float* __restrict__ Q, int ldq,
    int Klen, float* __restrict__ C, int ldc, int a0, float scale) {
  const int tid = threadIdx.x;
  const int a = a0 + (tid >> 4);
  const int b0 = (tid & 15) << 2;
  float acc0 = 0.f, acc1 = 0.f, acc2 = 0.f, acc3 = 0.f;
  const float4* Pr = (const float4*)(P + a * ldp);
  const float4* Q0 = (const float4*)(Q + (b0 + 0) * ldq);
  const float4* Q1 = (const float4*)(Q + (b0 + 1) * ldq);
  const float4* Q2 = (const float4*)(Q + (b0 + 2) * ldq);
  const float4* Q3 = (const float4*)(Q + (b0 + 3) * ldq);
  const int k4 = Klen >> 2;
#pragma unroll 4
  for (int k = 0; k < k4; k++) {
    float4 av = Pr[k];
    float4 bv;
    bv = Q0[k]; acc0 += av.x * bv.x + av.y * bv.y + av.z * bv.z + av.w * bv.w;
    bv = Q1[k]; acc1 += av.x * bv.x + av.y * bv.y + av.z * bv.z + av.w * bv.w;
    bv = Q2[k]; acc2 += av.x * bv.x + av.y * bv.y + av.z * bv.z + av.w * bv.w;
    bv = Q3[k]; acc3 += av.x * bv.x + av.y * bv.y + av.z * bv.z + av.w * bv.w;
  }
  float* Cr = C + a * ldc + b0;
  Cr[0] = acc0 * scale; Cr[1] = acc1 * scale;
  Cr[2] = acc2 * scale; Cr[3] = acc3 * scale;
}

// Register-resident pivot-free Gauss-Jordan inverse of a 64x64.
// 256 threads: thread owns CONTIGUOUS rows [16*r0, 16*r0+16) at column c=tid&63.
// Pivot loop unrolled x16 so every register-array index is compile-time static.
__device__ void gj_inverse_reg(const float* __restrict__ in,
                               float* __restrict__ out) {
  __shared__ __align__(16) float prow[2][64];
  __shared__ __align__(16) float pcol[2][64];
  const int tid = threadIdx.x;
  const int r0 = tid >> 6;        // 0..3 -> rows 16*r0 .. 16*r0+15
  const int c  = tid & 63;
  float v[16];
#pragma unroll
  for (int q = 0; q < 16; q++) v[q] = in[(r0 * 16 + q) * 64 + c];
  if (c == 0) {
#pragma unroll
    for (int q = 0; q < 16; q++) pcol[0][r0 * 16 + q] = v[q];
  }
  if (r0 == 0) prow[0][c] = v[0];
  __syncthreads();
  for (int po = 0; po < 4; po++) {
#pragma unroll
    for (int j = 0; j < 16; j++) {
      const int p = po * 16 + j;
      const int cur = p & 1, nxt = cur ^ 1;
      const float piv = prow[cur][p];
      const float dinv = 1.0f / piv;
      const float prc = prow[cur][c] * dinv;
      const bool cp = (c == p);
      const bool rown = (r0 == po);
      const float w = cp ? dinv : prc;
      float pc[16];
      {
        const float4* pcb = (const float4*)&pcol[cur][r0 * 16];
        float4 t0 = pcb[0], t1 = pcb[1], t2 = pcb[2], t3 = pcb[3];
        pc[0]=t0.x; pc[1]=t0.y; pc[2]=t0.z; pc[3]=t0.w;
        pc[4]=t1.x; pc[5]=t1.y; pc[6]=t1.z; pc[7]=t1.w;
        pc[8]=t2.x; pc[9]=t2.y; pc[10]=t2.z; pc[11]=t2.w;
        pc[12]=t3.x; pc[13]=t3.y; pc[14]=t3.z; pc[15]=t3.w;
      }
#pragma unroll
      for (int q = 0; q < 16; q++) {
        float base = cp ? 0.0f : v[q];
        v[q] = fmaf(-pc[q], w, base);
      }
      if (rown) v[j] = cp ? dinv : prc;
      if (p < 63) {
        const int pn = p + 1;
        if (c == pn) {
#pragma unroll
          for (int q = 0; q < 16; q++) pcol[nxt][r0 * 16 + q] = v[q];
        }
        if (r0 == (pn >> 4)) prow[nxt][c] = v[(j + 1) & 15];
      }
      __syncthreads();
    }
  }
#pragma unroll
  for (int q = 0; q < 16; q++) out[(r0 * 16 + q) * 64 + c] = v[q];
}

// ---------------- kernel 1: prep blocks (bid 0-2) + balanced gemm ----------------
// bid 0: S=inv(sx)+Mcat. 1: Sy=inv(sy)+Hinv. 2: H/HL/LHL.
// bid 3..290: split-K gemm, 2 mats x 4 m-tiles x 36 v-chunks (18/17 8-groups).
__global__ void __launch_bounds__(256, 2)
work_kernel(const float* __restrict__ fx, const float* __restrict__ fy,
            const float* __restrict__ tx, const float* __restrict__ ty,
            const float* __restrict__ sx, const float* __restrict__ sy,
            const float* __restrict__ ex, const float* __restrict__ ey) {
  __shared__ __align__(16) float shw[64 * SH2];   // 17KB multi-use
  const int bid = blockIdx.x;
  const int tid = threadIdx.x;

  if (bid >= 3) {
    float* Ws = shw;          // [8][64]
    float* Fs = shw + 512;    // [8][64]
    const int g   = bid - 3;            // 0..287
    const int mat = g / 144;
    const int r   = g % 144;
    const int mt  = r & 3;
    const int vs  = r >> 2;             // 0..35
    const int v0   = (vs < 13) ? vs * 144 : 1872 + (vs - 13) * 136;
    const int vlen = (vs < 13) ? 144 : 136;
    const float* __restrict__ F  = mat ? fy : fx;   // [VDIM][MDIM]
    const float* __restrict__ Wm = mat ? ty : tx;   // [KD][VDIM]
    float* out = g_AP[mat];
    const int m0 = mt * 64;
    const int kkA = tid & 7,  rowA = tid >> 3;
    const int kk2A = tid >> 6, colA = tid & 63;
    const int idxB = tid + 256;
    const int kkB = idxB & 7,  rowB = idxB >> 3;
    const int kk2B = idxB >> 6, colB = idxB & 63;
    const float* WA = Wm + rowA * VDIM + kkA;
    const float* WB = Wm + rowB * VDIM + kkB;
    const float* FA = F + kk2A * MDIM + m0 + colA;
    const float* FB = F + kk2B * MDIM + m0 + colB;
    const int tr = (tid >> 4) << 2;
    const int tc = (tid & 15) << 2;
    float acc[4][4];
#pragma unroll
    for (int i = 0; i < 4; i++)
#pragma unroll
      for (int j = 0; j < 4; j++) acc[i][j] = 0.f;

    float w0 = WA[v0], w1 = WB[v0];
    float f0 = FA[v0 * MDIM], f1 = FB[v0 * MDIM];
    for (int vv = v0; vv < v0 + vlen; vv += 8) {
      Ws[kkA * 64 + rowA] = w0;
      Ws[kkB * 64 + rowB] = w1;
      Fs[kk2A * 64 + colA] = f0;
      Fs[kk2B * 64 + colB] = f1;
      __syncthreads();
      const int nv = vv + 8;
      if (nv < v0 + vlen) {
        w0 = WA[nv]; w1 = WB[nv];
        f0 = FA[nv * MDIM]; f1 = FB[nv * MDIM];
      }
#pragma unroll
      for (int kk = 0; kk < 8; kk++) {
        float4 av = *(const float4*)&Ws[kk * 64 + tr];
        float4 bv = *(const float4*)&Fs[kk * 64 + tc];
        acc[0][0] += av.x * bv.x; acc[0][1] += av.x * bv.y; acc[0][2] += av.x * bv.z; acc[0][3] += av.x * bv.w;
        acc[1][0] += av.y * bv.x; acc[1][1] += av.y * bv.y; acc[1][2] += av.y * bv.z; acc[1][3] += av.y * bv.w;
        acc[2][0] += av.z * bv.x; acc[2][1] += av.z * bv.y; acc[2][2] += av.z * bv.z; acc[2][3] += av.z * bv.w;
        acc[3][0] += av.w * bv.x; acc[3][1] += av.w * bv.y; acc[3][2] += av.w * bv.z; acc[3][3] += av.w * bv.w;
      }
      __syncthreads();
    }
#pragma unroll
    for (int i = 0; i < 4; i++)
#pragma unroll
      for (int j = 0; j < 4; j++)
        atomicAdd(&out[(tr + i) * MDIM + m0 + tc + j], acc[i][j]);

  } else if (bid == 0) {
    // S = inv(sx), then M_j = S^T lx^j S (sqrt-weighted NT form), j=2,1,0
    gj_inverse_reg(sx, g_S);
    __syncthreads();
    for (int t = 0; t < 3; t++) {
      const int jc = t * 64;
      for (int i = tid; i < 4096; i += 256) {
        int a = i >> 6, ii = i & 63;
        float w = (t == 0) ? ex[ii] : ((t == 1) ? sqrtf(ex[ii]) : 1.0f);
        shw[a * SH2 + ii] = g_S[ii * 64 + a] * w;
      }
      __syncthreads();
      for (int a0 = 0; a0 < 64; a0 += 16)
        mm_nt_16(shw, SH2, shw, SH2, 64, g_Mcat + jc, 192, a0, 1.0f);
      __syncthreads();
    }
  } else if (bid == 1) {
    // Sy = inv(sy), then Hinv = Sy Sy^T
    gj_inverse_reg(sy, g_Sy);
    __syncthreads();
    for (int a0 = 0; a0 < 64; a0 += 16)
      mm_nt_16(g_Sy, 64, g_Sy, 64, 64, g_Hinv, 64, a0, 1.0f);
  } else {
    // H = sy^T sy; HL = H.*(ey_r+ey_c); LHL = ey_r.*H.*ey_c
    for (int i = tid; i < 4096; i += 256) {
      int a = i >> 6, rr = i & 63;
      shw[a * SH2 + rr] = sy[rr * 64 + a];
    }
    __syncthreads();
    for (int a0 = 0; a0 < 64; a0 += 16)
      mm_nt_16(shw, SH2, shw, SH2, 64, g_H, 64, a0, 1.0f);
    __syncthreads();
    for (int i = tid; i < 4096; i += 256) {
      int rr = i >> 6, cc = i & 63;
      float h = g_H[i];
      g_HL[i]  = h * (ey[rr] + ey[cc]);
      g_LHL[i] = ey[rr] * h * ey[cc];
    }
  }
}

// ---------------- kernel 2: solve (8-CTA cluster) ----------------
__global__ void __cluster_dims__(8, 1, 1) __launch_bounds__(256, 1)
solve_kernel(float* __restrict__ outp) {
  __shared__ __align__(16) float sh[11776];   // 47KB multi-use
  float* Qs = sh + 4352;                      // Mcat slab stage [64][SH2]
  const int rk = blockIdx.x;       // cluster rank 0..7
  const int tid = threadIdx.x;

  // ---- Phase A: one G/T1 slab + one LP slab per rank; prestage Mcat ----
  if (rk < 4) {
    mm_nt_16(g_AP[0], MDIM, g_AP[0], MDIM, MDIM, g_G, 64, rk * 16, 1.0f);
  } else {
    mm_nt_16(g_AP[1], MDIM, g_AP[0], MDIM, MDIM, g_T1, 64, (rk - 4) * 16, 1.0f);
  }
  {
    // LP: rank r -> half t=r>>2, slab a0=(r&3)*16. HL/LHL symmetric -> NT ok.
    const int t = rk >> 2;
    const int a0 = (rk & 3) * 16;
    const float* Q = t ? g_LHL : g_HL;
    const float scale = t ? 1.0f : -1.0f;
    const int off = t ? 64 : 0;
    mm_nt_16(g_Hinv, 64, Q, 64, 64, g_LP + off, 128, a0, scale);
  }
  if (rk < 6) {
    // prestage Mcat slab t = rk>>1 (symmetric slab: Qs[b][k] = Mcat[b][jc+k])
    const int jc = (rk >> 1) * 64;
    for (int i = tid; i < 4096; i += 256) {
      int b = i >> 6, k = i & 63;
      Qs[b * SH2 + k] = g_Mcat[b * 192 + jc + k];
    }
  }
  cluster_sync_fence();

  // ---- Phase B: Ginv = inv(G) on rank 0 ----
  if (rk == 0) gj_inverse_reg(g_G, g_Ginv);
  cluster_sync_fence();

  // ---- Phase C: stage GinvT; ranks 0-5: 2 NT units; ranks 6-7: 2 X0 units ----
  for (int i = tid; i < 4096; i += 256) {
    int b = i >> 6, u = i & 63;
    sh[b * SH2 + u] = g_Ginv[u * 64 + b];     // GinvT
  }
  __syncthreads();
  if (rk < 6) {
    const int jc = (rk >> 1) * 64;
    const int a0 = (rk & 1) * 32;
    mm_nt_16(sh, SH2, Qs, SH2, 64, g_NT + jc * 64, 64, a0, 1.0f);
    mm_nt_16(sh, SH2, Qs, SH2, 64, g_NT + jc * 64, 64, a0 + 16, 1.0f);
  } else {
    const int base = (rk - 6) * 32;
    mm_nt_16(g_T1, 64, sh, SH2, 64, g_X0, 64, base, 1.0f);
    mm_nt_16(g_T1, 64, sh, SH2, 64, g_X0, 64, base + 16, 1.0f);
  }
  cluster_sync_fence();

  // ---- Phase D: Richardson iterations; CTA owns 8 rows ----
  const int rowbase = rk * 8;
  float* Vcs = sh;                 // [64][128] = 8192 floats
  float* LPs = sh + 8192;          // [8][128]  = 1024 floats
  float* Xs  = sh + 8192 + 1024;   // [8][SH2]  = 544 floats
  for (int i = tid; i < 1024; i += 256)
    LPs[i] = g_LP[(rowbase + (i >> 7)) * 128 + (i & 127)];
  for (int i = tid; i < 512; i += 256) {
    int a = i >> 6, b = i & 63;
    Xs[a * SH2 + b] = g_X0[(rowbase + a) * 64 + b];
  }
  const int a    = tid >> 5;       // 0..7 local row
  const int lane = tid & 31;
  float x0v0 = g_X0[(rowbase + a) * 64 + lane];
  float x0v1 = g_X0[(rowbase + a) * 64 + lane + 32];
  __syncthreads();

  for (int it = 0; it < NITER; it++) {
    float* Vbuf = g_Vd[it & 1];
    // V[a][c] = sum_k Xs[a][k] * NT[c][k], cols c = lane + 32j, j=0..5
    float vacc[6] = {0.f, 0.f, 0.f, 0.f, 0.f, 0.f};
    const float4* xr = (const float4*)(Xs + a * SH2);
    const float4* nt0 = (const float4*)(g_NT + (lane +   0) * 64);
    const float4* nt1 = (const float4*)(g_NT + (lane +  32) * 64);
    const float4* nt2 = (const float4*)(g_NT + (lane +  64) * 64);
    const float4* nt3 = (const float4*)(g_NT + (lane +  96) * 64);
    const float4* nt4 = (const float4*)(g_NT + (lane + 128) * 64);
    const float4* nt5 = (const float4*)(g_NT + (lane + 160) * 64);
#pragma unroll
    for (int k4 = 0; k4 < 16; k4++) {
      float4 xv4 = xr[k4];
      float4 n;
      n = nt0[k4]; vacc[0] += xv4.x*n.x + xv4.y*n.y + xv4.z*n.z + xv4.w*n.w;
      n = nt1[k4]; vacc[1] += xv4.x*n.x + xv4.y*n.y + xv4.z*n.z + xv4.w*n.w;
      n = nt2[k4]; vacc[2] += xv4.x*n.x + xv4.y*n.y + xv4.z*n.z + xv4.w*n.w;
      n = nt3[k4]; vacc[3] += xv4.x*n.x + xv4.y*n.y + xv4.z*n.z + xv4.w*n.w;
      n = nt4[k4]; vacc[4] += xv4.x*n.x + xv4.y*n.y + xv4.z*n.z + xv4.w*n.w;
      n = nt5[k4]; vacc[5] += xv4.x*n.x + xv4.y*n.y + xv4.z*n.z + xv4.w*n.w;
    }
    // write V cols 64..191 (j=2..5) to global for cluster exchange
    Vbuf[(rowbase + a) * 128 + lane +  0] = vacc[2];
    Vbuf[(rowbase + a) * 128 + lane + 32] = vacc[3];
    Vbuf[(rowbase + a) * 128 + lane + 64] = vacc[4];
    Vbuf[(rowbase + a) * 128 + lane + 96] = vacc[5];
    cluster_sync_fence();
    // stage full Vc (64 rows x 128) into shared
    for (int i = tid; i < 8192; i += 256) Vcs[i] = Vbuf[i];
    __syncthreads();
    // corr[a][b] = sum_{u<64} LP[a][u]*Vcs[u][b] + LP[a][64+u]*Vcs[u][64+b]
    float c0 = 0.f, c1 = 0.f;
#pragma unroll 8
    for (int u = 0; u < 64; u++) {
      float lpA = LPs[a * 128 + u];
      float lpB = LPs[a * 128 + 64 + u];
      const float* vr = Vcs + u * 128;
      c0 += lpA * vr[lane]      + lpB * vr[64 + lane];
      c1 += lpA * vr[lane + 32] + lpB * vr[96 + lane];
    }
    float xn0 = x0v0 - LMBDA * (vacc[0] + c0);
    float xn1 = x0v1 - LMBDA * (vacc[1] + c1);
    if (it == NITER - 1) {
      outp[(rowbase + a) * 64 + lane]      = xn0;
      outp[(rowbase + a) * 64 + lane + 32] = xn1;
    } else {
      __syncthreads();           // everyone done reading Xs/Vcs
      Xs[a * SH2 + lane]      = xn0;
      Xs[a * SH2 + lane + 32] = xn1;
      __syncthreads();
    }
  }

  // ---- Epilogue: zero split-K accumulators for the next run ----
  {
    float4 z = make_float4(0.f, 0.f, 0.f, 0.f);
    float4* p = (float4*)g_AP;              // 8192 float4 total
    const int base = rk * 1024;             // 1024 float4 per CTA
    for (int i = tid; i < 1024; i += 256) p[base + i] = z;
  }
}

// ---------------- launch ----------------
extern "C" void kernel_launch(void* const* d_in, const int* in_sizes, int n_in,
                              void* d_out, int out_size) {
  const float* fx = (const float*)d_in[0];   // [1,5000,256]
  const float* fy = (const float*)d_in[1];   // [1,5000,256]
  const float* ex = (const float*)d_in[2];   // [1,64]
  const float* ey = (const float*)d_in[3];   // [1,64]
  const float* tx = (const float*)d_in[4];   // [1,64,5000]
  const float* ty = (const float*)d_in[5];   // [1,64,5000]
  const float* sx = (const float*)d_in[6];   // [1,64,64]
  const float* sy = (const float*)d_in[7];   // [1,64,64]
  float* out = (float*)d_out;                // [1,64,64] float32

  work_kernel<<<291, 256>>>(fx, fy, tx, ty, sx, sy, ex, ey);
  solve_kernel<<<8, 256>>>(out);
}